// round 12
// baseline (speedup 1.0000x reference)
#include <cuda_runtime.h>
#include <cstdint>

// GCMConv on 8x8x16x16 lattice — tensor-core (tf32) M-build.
//   B[w, plane, site]  (w=0..15 transported T, plane = 9 re + 9 im)
//   G[72, 18NS] = [W1;W2] @ B   via mma.sync m16n8k8 tf32
//   M_uv = G1_uv + G2_uv^dag (+ c3 I in apply)
//   w_out[u] = M_8' + sum_c w_c @ M_c' + w_c^dag @ M_{4+c}'
// transport/apply stay fp32 (exact); only the 32-term weighted sum is tf32.

#define NS 16384

__device__ float  g_B[16 * 18 * NS];   // [(w*18 + plane)*NS + site], tf32-truncated
__device__ float2 g_Wc[4 * 9 * NS];    // [(c*9 + e)*NS + site] own-site fields
__device__ float2 g_M[36 * 9 * NS];    // [((u*9+v)*9 + e)*NS + site] combined M

__device__ __forceinline__ uint32_t tf32_bits(float x) {
    uint32_t u;
    asm("cvt.rna.tf32.f32 %0, %1;" : "=r"(u) : "f"(x));
    return u;
}

// ---------------------------------------------------------------------------
__global__ __launch_bounds__(256) void transport_kernel(const float* __restrict__ x) {
    int g = blockIdx.x * 256 + threadIdx.x;   // 0 .. 4*NS-1
    int site = g & (NS - 1);
    int a = g >> 14;                           // axis 0..3

    // periodic +1 neighbor; dims (8,8,16,16), strides (2048,256,16,1)
    int d3 = site & 15, d2 = (site >> 4) & 15, d1 = (site >> 8) & 7, d0 = (site >> 11) & 7;
    int nbr;
    if (a == 0)      nbr = site + ((((d0 + 1) & 7) - d0) << 11);
    else if (a == 1) nbr = site + ((((d1 + 1) & 7) - d1) << 8);
    else if (a == 2) nbr = site + ((((d2 + 1) & 15) - d2) << 4);
    else             nbr = site + (((d3 + 1) & 15) - d3);

    float Ur[3][3], Ui[3][3];
    {
        const float2* up = (const float2*)(x + site * 144 + a * 18);
#pragma unroll
        for (int m = 0; m < 9; m++) {
            float2 t = up[m];
            Ur[m / 3][m % 3] = t.x;
            Ui[m / 3][m % 3] = t.y;
        }
    }

#pragma unroll
    for (int c = 0; c < 4; c++) {
        float Wr[3][3], Wi[3][3];
        const float2* wp = (const float2*)(x + nbr * 144 + (4 + c) * 18);
#pragma unroll
        for (int m = 0; m < 9; m++) {
            float2 t = wp[m];
            Wr[m / 3][m % 3] = t.x;
            Wi[m / 3][m % 3] = t.y;
        }
        // t1 = U @ W
        float t1r[3][3], t1i[3][3];
#pragma unroll
        for (int i = 0; i < 3; i++)
#pragma unroll
            for (int kk = 0; kk < 3; kk++) {
                float cr = 0.f, ci = 0.f;
#pragma unroll
                for (int j = 0; j < 3; j++) {
                    cr += Ur[i][j] * Wr[j][kk] - Ui[i][j] * Wi[j][kk];
                    ci += Ur[i][j] * Wi[j][kk] + Ui[i][j] * Wr[j][kk];
                }
                t1r[i][kk] = cr;
                t1i[i][kk] = ci;
            }
        // T = t1 @ U^dag ; write tf32-truncated planes
        int w = a * 4 + c;
#pragma unroll
        for (int i = 0; i < 3; i++)
#pragma unroll
            for (int kk = 0; kk < 3; kk++) {
                float cr = 0.f, ci = 0.f;
#pragma unroll
                for (int j = 0; j < 3; j++) {
                    float br = Ur[kk][j], bi = -Ui[kk][j];
                    cr += t1r[i][j] * br - t1i[i][j] * bi;
                    ci += t1r[i][j] * bi + t1i[i][j] * br;
                }
                int e = i * 3 + kk;
                g_B[(w * 18 + e) * NS + site]     = __uint_as_float(tf32_bits(cr));
                g_B[(w * 18 + 9 + e) * NS + site] = __uint_as_float(tf32_bits(ci));
            }
    }

    // own-site field: thread (site, a) copies channel c = a (full fp32)
    {
        const float2* wp = (const float2*)(x + site * 144 + (4 + a) * 18);
#pragma unroll
        for (int m = 0; m < 9; m++)
            g_Wc[(a * 9 + m) * NS + site] = wp[m];
    }
}

// ---------------------------------------------------------------------------
// GEMM: per CTA, 8 sites. G[72,16] @ B[16, 9 planes x 8 sites] per chunk
// (chunk 0 = re planes, chunk 1 = im planes), combine G1/G2 in smem, write M.
__global__ __launch_bounds__(128) void gemm_kernel(const float* __restrict__ weight) {
    __shared__ float Ws[80 * 17];        // stacked [W1;W2;0pad], stride 17 (bank pad)
    __shared__ float Bs[16 * 72];        // [k][plane*8 + s]
    __shared__ float Cs[80 * 72];        // [row][plane*8 + s]

    const int tid = threadIdx.x;
    const int siteBase = blockIdx.x * 8;
    const int lane = tid & 31, warp = tid >> 5;
    const int lg = lane >> 2, lt = lane & 3;

    // build Ws (tf32-truncated weights)
    for (int s = tid; s < 80 * 16; s += 128) {
        int row = s >> 4, k = s & 15;
        float val = 0.f;
        if (row < 36)      val = weight[(row / 9) * 297 + (row % 9) * 33 + k];
        else if (row < 72) { int r = row - 36; val = weight[(r / 9) * 297 + (r % 9) * 33 + 16 + k]; }
        Ws[row * 17 + k] = __uint_as_float(tf32_bits(val));
    }
    __syncthreads();

    float* mg = reinterpret_cast<float*>(g_M);

#pragma unroll
    for (int chunk = 0; chunk < 2; chunk++) {
        // stage B tile: 16 k x 9 planes x 8 sites
        for (int s = tid; s < 16 * 72; s += 128) {
            int k = s / 72, rem = s % 72, p = rem >> 3, si = rem & 7;
            Bs[s] = g_B[(k * 18 + chunk * 9 + p) * NS + siteBase + si];
        }
        __syncthreads();

        // 45 (Mtile, plane) pairs over 4 warps
        for (int t = warp; t < 45; t += 4) {
            int mt = t / 9, p = t % 9;
            float d0 = 0.f, d1 = 0.f, d2 = 0.f, d3 = 0.f;
#pragma unroll
            for (int ks = 0; ks < 2; ks++) {
                uint32_t a0 = __float_as_uint(Ws[(mt * 16 + lg) * 17 + ks * 8 + lt]);
                uint32_t a1 = __float_as_uint(Ws[(mt * 16 + lg + 8) * 17 + ks * 8 + lt]);
                uint32_t a2 = __float_as_uint(Ws[(mt * 16 + lg) * 17 + ks * 8 + lt + 4]);
                uint32_t a3 = __float_as_uint(Ws[(mt * 16 + lg + 8) * 17 + ks * 8 + lt + 4]);
                uint32_t b0 = __float_as_uint(Bs[(ks * 8 + lt) * 72 + p * 8 + lg]);
                uint32_t b1 = __float_as_uint(Bs[(ks * 8 + lt + 4) * 72 + p * 8 + lg]);
                asm volatile(
                    "mma.sync.aligned.m16n8k8.row.col.f32.tf32.tf32.f32 "
                    "{%0,%1,%2,%3},{%4,%5,%6,%7},{%8,%9},{%0,%1,%2,%3};"
                    : "+f"(d0), "+f"(d1), "+f"(d2), "+f"(d3)
                    : "r"(a0), "r"(a1), "r"(a2), "r"(a3), "r"(b0), "r"(b1));
            }
            Cs[(mt * 16 + lg) * 72 + p * 8 + 2 * lt]         = d0;
            Cs[(mt * 16 + lg) * 72 + p * 8 + 2 * lt + 1]     = d1;
            Cs[(mt * 16 + lg + 8) * 72 + p * 8 + 2 * lt]     = d2;
            Cs[(mt * 16 + lg + 8) * 72 + p * 8 + 2 * lt + 1] = d3;
        }
        __syncthreads();

        // combine: M_uv[e] = G1_uv[e] +/- G2_uv[eT]  (re: +, im: -)
        const float sign = (chunk == 0) ? 1.f : -1.f;
        for (int n = tid; n < 36 * 72; n += 128) {
            int uv = n / 72, rem = n % 72, e = rem >> 3, s = rem & 7;
            int eT = (e % 3) * 3 + e / 3;
            float val = Cs[uv * 72 + e * 8 + s] + sign * Cs[(36 + uv) * 72 + eT * 8 + s];
            mg[((uv * 9 + e) * NS + siteBase + s) * 2 + chunk] = val;
        }
        __syncthreads();
    }
}

// ---------------------------------------------------------------------------
__global__ __launch_bounds__(128) void apply_kernel(const float* __restrict__ x,
                                                    const float* __restrict__ weight,
                                                    float* __restrict__ out) {
    __shared__ float c3s[9];
    const int tid = threadIdx.x;
    int g = blockIdx.x * 128 + tid;
    int site = g & (NS - 1);
    int u = g >> 14;  // uniform per block
    if (tid < 9) c3s[tid] = weight[u * 297 + tid * 33 + 32];
    __syncthreads();

    // copy gauge link channel u to output
    {
        const float2* src = (const float2*)(x + site * 144 + u * 18);
        float2* dst = (float2*)(out + site * 144 + u * 18);
#pragma unroll
        for (int m = 0; m < 9; m++) dst[m] = src[m];
    }

    float accr[9], acci[9];
    // v = 8: acc = M_{u,8} + c3 I
    {
        const float2* mp = g_M + (u * 9 + 8) * 9 * NS;
#pragma unroll
        for (int e = 0; e < 9; e++) {
            float2 t = mp[e * NS + site];
            accr[e] = t.x;
            acci[e] = t.y;
        }
        float c3 = c3s[8];
        accr[0] += c3; accr[4] += c3; accr[8] += c3;
    }

#pragma unroll
    for (int c = 0; c < 4; c++) {
        float wr[9], wi[9];
#pragma unroll
        for (int e = 0; e < 9; e++) {
            float2 t = g_Wc[(c * 9 + e) * NS + site];
            wr[e] = t.x;
            wi[e] = t.y;
        }
        // v = c: acc += w_c @ (M + c3 I)
        {
            float nr[9], ni[9];
            const float2* mp = g_M + (u * 9 + c) * 9 * NS;
#pragma unroll
            for (int e = 0; e < 9; e++) {
                float2 t = mp[e * NS + site];
                nr[e] = t.x;
                ni[e] = t.y;
            }
            float c3 = c3s[c];
            nr[0] += c3; nr[4] += c3; nr[8] += c3;
#pragma unroll
            for (int i = 0; i < 3; i++)
#pragma unroll
                for (int kk = 0; kk < 3; kk++) {
                    float cr = accr[i * 3 + kk], ci = acci[i * 3 + kk];
#pragma unroll
                    for (int j = 0; j < 3; j++) {
                        cr += wr[i * 3 + j] * nr[j * 3 + kk] - wi[i * 3 + j] * ni[j * 3 + kk];
                        ci += wr[i * 3 + j] * ni[j * 3 + kk] + wi[i * 3 + j] * nr[j * 3 + kk];
                    }
                    accr[i * 3 + kk] = cr;
                    acci[i * 3 + kk] = ci;
                }
        }
        // v = 4+c: acc += w_c^dag @ (M + c3 I)
        {
            float nr[9], ni[9];
            const float2* mp = g_M + (u * 9 + 4 + c) * 9 * NS;
#pragma unroll
            for (int e = 0; e < 9; e++) {
                float2 t = mp[e * NS + site];
                nr[e] = t.x;
                ni[e] = t.y;
            }
            float c3 = c3s[4 + c];
            nr[0] += c3; nr[4] += c3; nr[8] += c3;
#pragma unroll
            for (int i = 0; i < 3; i++)
#pragma unroll
                for (int kk = 0; kk < 3; kk++) {
                    float cr = accr[i * 3 + kk], ci = acci[i * 3 + kk];
#pragma unroll
                    for (int j = 0; j < 3; j++) {
                        // conj(w[j][i]) * N[j][kk]
                        cr += wr[j * 3 + i] * nr[j * 3 + kk] + wi[j * 3 + i] * ni[j * 3 + kk];
                        ci += wr[j * 3 + i] * ni[j * 3 + kk] - wi[j * 3 + i] * nr[j * 3 + kk];
                    }
                    accr[i * 3 + kk] = cr;
                    acci[i * 3 + kk] = ci;
                }
        }
    }

    float2* dst = (float2*)(out + site * 144 + (4 + u) * 18);
#pragma unroll
    for (int m = 0; m < 9; m++)
        dst[m] = make_float2(accr[m], acci[m]);
}

// ---------------------------------------------------------------------------
extern "C" void kernel_launch(void* const* d_in, const int* in_sizes, int n_in,
                              void* d_out, int out_size) {
    const float* x = (const float*)d_in[0];
    const float* weight = (const float*)d_in[1];
    float* out = (float*)d_out;

    transport_kernel<<<4 * NS / 256, 256>>>(x);
    gemm_kernel<<<NS / 8, 128>>>(weight);
    apply_kernel<<<4 * NS / 128, 128>>>(x, weight, out);
}

// round 13
// speedup vs baseline: 1.0283x; 1.0283x over previous
#include <cuda_runtime.h>
#include <cstdint>

// GCMConv on 8x8x16x16 lattice — fused tensor-core (tf32) pipeline.
//   B[(w*9+e)*NS + site] float2 (re,im), tf32-truncated  -> GEMM cols = 2*site+ri
//   C[80 rows][9 e][16 cols] = [W1;W2;pad] @ B   (mma m16n8k8 tf32, in smem)
//   M_uv[e] (re) = C1[e][2s]   + C2[eT][2s]
//   M_uv[e] (im) = C1[e][2s+1] - C2[eT][2s+1]
//   w_out[u] = (M_u8 + c3 I) + sum_c w_c @ (M_uc + c3 I) + w_c^dag @ (M_u,4+c + c3 I)
// transport + apply stay fp32; only the 32-term weighted sum is tf32.

#define NS 16384

__device__ float2 g_B[16 * 9 * NS];   // [(w*9+e)*NS + site]

__device__ __forceinline__ uint32_t tf32_bits(float x) {
    uint32_t u;
    asm("cvt.rna.tf32.f32 %0, %1;" : "=r"(u) : "f"(x));
    return u;
}

// ---------------------------------------------------------------------------
__global__ __launch_bounds__(256) void transport_kernel(const float* __restrict__ x) {
    int g = blockIdx.x * 256 + threadIdx.x;   // 0 .. 4*NS-1
    int site = g & (NS - 1);
    int a = g >> 14;                           // axis 0..3

    int d3 = site & 15, d2 = (site >> 4) & 15, d1 = (site >> 8) & 7, d0 = (site >> 11) & 7;
    int nbr;
    if (a == 0)      nbr = site + ((((d0 + 1) & 7) - d0) << 11);
    else if (a == 1) nbr = site + ((((d1 + 1) & 7) - d1) << 8);
    else if (a == 2) nbr = site + ((((d2 + 1) & 15) - d2) << 4);
    else             nbr = site + (((d3 + 1) & 15) - d3);

    float Ur[3][3], Ui[3][3];
    {
        const float2* up = (const float2*)(x + site * 144 + a * 18);
#pragma unroll
        for (int m = 0; m < 9; m++) {
            float2 t = up[m];
            Ur[m / 3][m % 3] = t.x;
            Ui[m / 3][m % 3] = t.y;
        }
    }

#pragma unroll
    for (int c = 0; c < 4; c++) {
        float Wr[3][3], Wi[3][3];
        const float2* wp = (const float2*)(x + nbr * 144 + (4 + c) * 18);
#pragma unroll
        for (int m = 0; m < 9; m++) {
            float2 t = wp[m];
            Wr[m / 3][m % 3] = t.x;
            Wi[m / 3][m % 3] = t.y;
        }
        float t1r[3][3], t1i[3][3];
#pragma unroll
        for (int i = 0; i < 3; i++)
#pragma unroll
            for (int kk = 0; kk < 3; kk++) {
                float cr = 0.f, ci = 0.f;
#pragma unroll
                for (int j = 0; j < 3; j++) {
                    cr += Ur[i][j] * Wr[j][kk] - Ui[i][j] * Wi[j][kk];
                    ci += Ur[i][j] * Wi[j][kk] + Ui[i][j] * Wr[j][kk];
                }
                t1r[i][kk] = cr;
                t1i[i][kk] = ci;
            }
        int w = a * 4 + c;
#pragma unroll
        for (int i = 0; i < 3; i++)
#pragma unroll
            for (int kk = 0; kk < 3; kk++) {
                float cr = 0.f, ci = 0.f;
#pragma unroll
                for (int j = 0; j < 3; j++) {
                    float br = Ur[kk][j], bi = -Ui[kk][j];
                    cr += t1r[i][j] * br - t1i[i][j] * bi;
                    ci += t1r[i][j] * bi + t1i[i][j] * br;
                }
                g_B[(w * 9 + i * 3 + kk) * NS + site] =
                    make_float2(__uint_as_float(tf32_bits(cr)), __uint_as_float(tf32_bits(ci)));
            }
    }
}

// ---------------------------------------------------------------------------
// Fused GEMM + apply. Block = 8 sites, 128 threads (4 warps).
// smem: Cs[80*144] | Ws[80*17] | Bs[16*152] | xs[8*146] | c3s[36]
#define CS_N   (80 * 144)
#define WS_OFF CS_N
#define BS_OFF (WS_OFF + 80 * 17)
#define XS_OFF (BS_OFF + 16 * 152)
#define C3_OFF (XS_OFF + 8 * 146)
#define SMEM_FLOATS (C3_OFF + 36)

__global__ __launch_bounds__(128) void fused_kernel(const float* __restrict__ x,
                                                    const float* __restrict__ weight,
                                                    float* __restrict__ out) {
    extern __shared__ float sm[];
    float* Cs = sm;
    float* Ws = sm + WS_OFF;
    float* Bs = sm + BS_OFF;
    float* xs = sm + XS_OFF;
    float* c3s = sm + C3_OFF;

    const int tid = threadIdx.x;
    const int siteBase = blockIdx.x * 8;
    const int lane = tid & 31, warp = tid >> 5;
    const int lg = lane >> 2, lt = lane & 3;

    // ---- stage Ws (tf32 weights, rows 0-35 = W1, 36-71 = W2, 72-79 = 0) ----
    for (int s = tid; s < 80 * 16; s += 128) {
        int row = s >> 4, k = s & 15;
        float val = 0.f;
        if (row < 36)      val = weight[(row / 9) * 297 + (row % 9) * 33 + k];
        else if (row < 72) { int r = row - 36; val = weight[(r / 9) * 297 + (r % 9) * 33 + 16 + k]; }
        Ws[row * 17 + k] = __uint_as_float(tf32_bits(val));
    }
    if (tid < 36) c3s[tid] = weight[(tid / 9) * 297 + (tid % 9) * 33 + 32];

    // ---- stage Bs: [k][p*16 + col], col = 2*(site-siteBase)+ri, stride 152 ----
    {
        const float4* b4 = reinterpret_cast<const float4*>(g_B);
        for (int i4 = tid; i4 < 576; i4 += 128) {
            int row = i4 >> 2, q = i4 & 3;           // row = w*9+p
            float4 v = b4[((row * NS + siteBase) >> 1) + q];
            float* d = Bs + (row / 9) * 152 + (row % 9) * 16 + q * 4;
            d[0] = v.x; d[1] = v.y; d[2] = v.z; d[3] = v.w;
        }
    }

    // ---- stage xs: 8 sites x 144 floats (stride 146) ----
    {
        const float4* x4 = reinterpret_cast<const float4*>(x + siteBase * 144);
        for (int i4 = tid; i4 < 288; i4 += 128) {
            float4 v = x4[i4];
            int flat = i4 * 4;
            int s = flat / 144, c = flat % 144;
            float* d = xs + s * 146 + c;
            d[0] = v.x; d[1] = v.y; d[2] = v.z; d[3] = v.w;
        }
    }
    __syncthreads();

    // ---- copy gauge links (channels 0-3) to out ----
    for (int i = tid; i < 576; i += 128) {
        int s = i / 72, c = i % 72;
        out[(siteBase + s) * 144 + c] = xs[s * 146 + c];
    }

    // ---- mma: 5 mtiles x 9 planes x 2 nhalves = 90 warp tiles ----
    for (int t = warp; t < 90; t += 4) {
        int mt = t / 18, rem = t % 18;
        int p = rem >> 1, nh = rem & 1;
        float d0 = 0.f, d1 = 0.f, d2 = 0.f, d3 = 0.f;
#pragma unroll
        for (int ks = 0; ks < 2; ks++) {
            uint32_t a0 = __float_as_uint(Ws[(mt * 16 + lg) * 17 + ks * 8 + lt]);
            uint32_t a1 = __float_as_uint(Ws[(mt * 16 + lg + 8) * 17 + ks * 8 + lt]);
            uint32_t a2 = __float_as_uint(Ws[(mt * 16 + lg) * 17 + ks * 8 + lt + 4]);
            uint32_t a3 = __float_as_uint(Ws[(mt * 16 + lg + 8) * 17 + ks * 8 + lt + 4]);
            uint32_t b0 = __float_as_uint(Bs[(ks * 8 + lt) * 152 + p * 16 + nh * 8 + lg]);
            uint32_t b1 = __float_as_uint(Bs[(ks * 8 + lt + 4) * 152 + p * 16 + nh * 8 + lg]);
            asm volatile(
                "mma.sync.aligned.m16n8k8.row.col.f32.tf32.tf32.f32 "
                "{%0,%1,%2,%3},{%4,%5,%6,%7},{%8,%9},{%0,%1,%2,%3};"
                : "+f"(d0), "+f"(d1), "+f"(d2), "+f"(d3)
                : "r"(a0), "r"(a1), "r"(a2), "r"(a3), "r"(b0), "r"(b1));
        }
        int cb = p * 16 + nh * 8;
        Cs[(mt * 16 + lg) * 144 + cb + 2 * lt]         = d0;
        Cs[(mt * 16 + lg) * 144 + cb + 2 * lt + 1]     = d1;
        Cs[(mt * 16 + lg + 8) * 144 + cb + 2 * lt]     = d2;
        Cs[(mt * 16 + lg + 8) * 144 + cb + 2 * lt + 1] = d3;
    }
    __syncthreads();

    // ---- apply: warp = u, lane = s + 8*tsub; tsub handles e = tsub, tsub+4, tsub+8
    {
        const int u = warp;
        const int s = lane & 7;
        const int tsub = lane >> 3;

        for (int e = tsub; e < 9; e += 4) {
            const int i = e / 3, kk = e % 3;
            float ar, ai;

            // v = 8 (A = I): acc = M_8[e] + c3 diag
            {
                const float* c1 = Cs + (u * 9 + 8) * 144;
                const float* c2 = Cs + (36 + u * 9 + 8) * 144;
                int eT = kk * 3 + i;
                ar = c1[e * 16 + 2 * s] + c2[eT * 16 + 2 * s];
                ai = c1[e * 16 + 2 * s + 1] - c2[eT * 16 + 2 * s + 1];
                if (i == kk) ar += c3s[u * 9 + 8];
            }

#pragma unroll
            for (int v = 0; v < 4; v++) {
                const float* c1a = Cs + (u * 9 + v) * 144;
                const float* c2a = Cs + (36 + u * 9 + v) * 144;
                const float* c1b = Cs + (u * 9 + 4 + v) * 144;
                const float* c2b = Cs + (36 + u * 9 + 4 + v) * 144;
                float c3a = c3s[u * 9 + v];
                float c3b = c3s[u * 9 + 4 + v];
                const float* wv = xs + s * 146 + (4 + v) * 18;
#pragma unroll
                for (int j = 0; j < 3; j++) {
                    int em = j * 3 + kk, emT = kk * 3 + j;
                    // M_v[j][kk]
                    float mr = c1a[em * 16 + 2 * s] + c2a[emT * 16 + 2 * s];
                    float mi = c1a[em * 16 + 2 * s + 1] - c2a[emT * 16 + 2 * s + 1];
                    if (j == kk) mr += c3a;
                    // A = w_v : w[i][j]
                    float wr = wv[(i * 3 + j) * 2], wi = wv[(i * 3 + j) * 2 + 1];
                    ar += wr * mr - wi * mi;
                    ai += wr * mi + wi * mr;
                    // M_{4+v}[j][kk]
                    float nr = c1b[em * 16 + 2 * s] + c2b[emT * 16 + 2 * s];
                    float ni = c1b[em * 16 + 2 * s + 1] - c2b[emT * 16 + 2 * s + 1];
                    if (j == kk) nr += c3b;
                    // A = w_v^dag : conj(w[j][i])
                    float vr = wv[(j * 3 + i) * 2], vi = wv[(j * 3 + i) * 2 + 1];
                    ar += vr * nr + vi * ni;
                    ai += vr * ni - vi * nr;
                }
            }

            float2* dst = (float2*)(out + (siteBase + s) * 144 + (4 + u) * 18);
            dst[e] = make_float2(ar, ai);
        }
    }
}

// ---------------------------------------------------------------------------
extern "C" void kernel_launch(void* const* d_in, const int* in_sizes, int n_in,
                              void* d_out, int out_size) {
    const float* x = (const float*)d_in[0];
    const float* weight = (const float*)d_in[1];
    float* out = (float*)d_out;

    static_assert(SMEM_FLOATS * 4 < 100 * 1024, "smem");
    cudaFuncSetAttribute(fused_kernel, cudaFuncAttributeMaxDynamicSharedMemorySize,
                         SMEM_FLOATS * 4);

    transport_kernel<<<4 * NS / 256, 256>>>(x);
    fused_kernel<<<NS / 8, 128, SMEM_FLOATS * 4>>>(x, weight, out);
}